// round 15
// baseline (speedup 1.0000x reference)
#include <cuda_runtime.h>
#include <cuda_fp16.h>
#include <math.h>
#include <stdint.h>

// ---------------- problem constants ----------------
#define Ss    512
#define Hh    768
#define Vv    30522
#define Pp    512
#define H3    2304
#define Mrows 4096
#define KDIM  2304
#define NCHUNKS 36          // 2304 / 64
#define VPAD  30592
#define MC    4352          // max compact rows
#define NT3   239           // GEMM3 N-tiles ((Vv+127)/128)
#define NT1   18            // GEMM1/2 N-tiles (H3/128)

// ---------------- device scratch (allocation-free) ----------------
__device__ __half g_act_hi[(size_t)MC * KDIM];
__device__ float  g_bufF [(size_t)MC * KDIM];
__device__ __half g_w1_h[(size_t)H3 * KDIM];
__device__ __half g_w2_h[(size_t)H3 * KDIM];
__device__ __half g_wo_h[(size_t)VPAD * KDIM];   // pad rows stay zero
__device__ int    g_mask_mode;
__device__ int    g_rowmap[MC];
__device__ int    g_mkept;
__device__ int    g_mpad;
__device__ int    g_const_slot;

// ---------------- helpers ----------------
__device__ __forceinline__ uint32_t smem_u32(const void* p) {
    uint32_t a;
    asm("{ .reg .u64 t; cvta.to.shared.u64 t, %1; cvt.u32.u64 %0, t; }"
        : "=r"(a) : "l"(p));
    return a;
}
__device__ __forceinline__ void cp16(uint32_t s, const void* g) {
    asm volatile("cp.async.cg.shared.global [%0], [%1], 16;" :: "r"(s), "l"(g));
}
__device__ __forceinline__ void ldm_x4(uint32_t* r, uint32_t addr) {
    asm volatile("ldmatrix.sync.aligned.m8n8.x4.shared.b16 {%0,%1,%2,%3}, [%4];"
                 : "=r"(r[0]), "=r"(r[1]), "=r"(r[2]), "=r"(r[3]) : "r"(addr));
}
__device__ __forceinline__ void mma_fp16(float* c, const uint32_t* a, const uint32_t* b) {
    asm volatile(
        "mma.sync.aligned.m16n8k16.row.col.f32.f16.f16.f32 "
        "{%0,%1,%2,%3}, {%4,%5,%6,%7}, {%8,%9}, {%0,%1,%2,%3};"
        : "+f"(c[0]), "+f"(c[1]), "+f"(c[2]), "+f"(c[3])
        : "r"(a[0]), "r"(a[1]), "r"(a[2]), "r"(a[3]), "r"(b[0]), "r"(b[1]));
}
__device__ __forceinline__ bool read_mask(const void* mask, int row, int mode) {
    if (mode == 0)      return ((const int*)mask)[row] != 0;
    else if (mode == 1) return ((const float*)mask)[row] != 0.0f;
    else                return ((const unsigned char*)mask)[row] != 0;
}

// ---------------- shared transpose role: W[KDIM,N] fp32 -> T[N,KDIM] fp16 ------
__device__ void transpose_role(const float* __restrict__ W,
                               __half* __restrict__ T,
                               int N, int tb, int nblocks) {
    __shared__ float tsh[32 * 33];
    int tx = threadIdx.x & 31, ty = threadIdx.x >> 5;
    const int ntN = (N + 31) / 32;
    const int total = ntN * (KDIM / 32);
    for (int tile = tb; tile < total; tile += nblocks) {
        int tk = tile / ntN, tn = tile % ntN;
        int k0 = tk * 32, n0 = tn * 32;
#pragma unroll
        for (int i = 0; i < 4; i++) {
            int k = k0 + ty + i * 8;
            int n = n0 + tx;
            tsh[(ty + i * 8) * 33 + tx] = (n < N) ? W[(size_t)k * N + n] : 0.0f;
        }
        __syncthreads();
#pragma unroll
        for (int i = 0; i < 4; i++) {
            int n = n0 + ty + i * 8;
            int k = k0 + tx;
            if (n < N)
                T[(size_t)n * KDIM + k] = __float2half_rn(tsh[tx * 33 + ty + i * 8]);
        }
        __syncthreads();
    }
}

// ---------------- compact (includes mask-dtype detect) ----------------
__global__ void compact_kernel(const void* __restrict__ mask) {
    __shared__ int cnt[1024];
    __shared__ int firstm;
    __shared__ unsigned int s_not01, s_notf;
    __shared__ int s_mode;
    int t = threadIdx.x;
    if (t == 0) { firstm = 0x7FFFFFFF; s_not01 = 0u; s_notf = 0u; }
    __syncthreads();
    {
        unsigned int v = ((const unsigned int*)mask)[t];
        unsigned int a = v & ~1u;
        unsigned int b = (v != 0u && v != 0x3F800000u) ? 1u : 0u;
        if (a) atomicOr(&s_not01, a);
        if (b) atomicOr(&s_notf, 1u);
    }
    __syncthreads();
    if (t == 0) {
        int mode = (s_not01 == 0u) ? 0 : ((s_notf == 0u) ? 1 : 2);
        s_mode = mode;
        g_mask_mode = mode;
    }
    __syncthreads();
    int mode = s_mode;

    bool keep[4];
    int c = 0, fm = 0x7FFFFFFF;
#pragma unroll
    for (int j = 0; j < 4; j++) {
        int row = t * 4 + j;
        bool m = read_mask(mask, row, mode);
        keep[j] = m;
        c += m ? 1 : 0;
        if (!m && row < fm) fm = row;
    }
    if (fm != 0x7FFFFFFF) atomicMin(&firstm, fm);
    cnt[t] = c;
    __syncthreads();
    for (int o = 1; o < 1024; o <<= 1) {
        int v = (t >= o) ? cnt[t - o] : 0;
        __syncthreads();
        cnt[t] += v;
        __syncthreads();
    }
    int off = cnt[t] - c;
#pragma unroll
    for (int j = 0; j < 4; j++)
        if (keep[j]) g_rowmap[off++] = t * 4 + j;
    __syncthreads();
    int total = cnt[1023];
    if (t == 0) {
        int cs = (firstm == 0x7FFFFFFF) ? -1 : firstm;
        g_mkept = total;
        g_rowmap[total] = cs;
        g_const_slot = cs;
        g_mpad = ((total + 1 + 127) / 128) * 128;
    }
    __syncthreads();
    int tot1 = cnt[1023] + 1;
    for (int i = tot1 + t; i < MC; i += 1024) g_rowmap[i] = -1;
}

// ---------------- concat build (compact) + fused W1 transpose ----------------
#define TRB_SMALL 512

__global__ void concat_fused_kernel(const float* __restrict__ x,
                                    const int* __restrict__ left,
                                    const int* __restrict__ right,
                                    const float* __restrict__ pos_table,
                                    __half* __restrict__ hi,
                                    const float* __restrict__ W1,
                                    __half* __restrict__ w1h) {
    int bid = blockIdx.x;
    if (bid >= MC) {
        transpose_role(W1, w1h, H3, bid - MC, TRB_SMALL);
        return;
    }
    int ci = bid;
    int mpad = g_mpad, mk = g_mkept;
    if (ci >= mpad) return;
    size_t o = (size_t)ci * H3;

    if (ci >= mk) {
        __half hv = (ci == mk) ? __float2half_rn(-100.0f) : __float2half_rn(0.0f);
        for (int i = threadIdx.x; i < H3; i += blockDim.x)
            hi[o + i] = hv;
        return;
    }

    int row = g_rowmap[ci];
    int b = row >> 9;
    int s = row & (Ss - 1);
    int l = left[row], r = right[row];
    int rel = s - l;
    rel = rel < 0 ? 0 : (rel > (Pp - 1) ? (Pp - 1) : rel);

    const float* xl = x + ((size_t)b * Ss + l) * Hh;
    const float* xr = x + ((size_t)b * Ss + r) * Hh;
    const float* pp = pos_table + (size_t)rel * Hh;

    for (int i = threadIdx.x; i < Hh; i += blockDim.x) {
        hi[o + i]          = __float2half_rn(xl[i]);
        hi[o + Hh + i]     = __float2half_rn(xr[i]);
        hi[o + 2*Hh + i]   = __float2half_rn(pp[i]);
    }
}

// ---------------- GELU + LayerNorm + fused weight transpose ----------------
__global__ void gelu_ln_fused_kernel(const float* __restrict__ in,
                                     const float* __restrict__ g,
                                     const float* __restrict__ be,
                                     __half* __restrict__ hi,
                                     const float* __restrict__ Wsrc,
                                     __half* __restrict__ Tdst,
                                     int Nw, int trb) {
    int bid = blockIdx.x;
    if (bid >= MC) {
        transpose_role(Wsrc, Tdst, Nw, bid - MC, trb);
        return;
    }
    if (bid >= g_mpad) return;
    const float* p = in + (size_t)bid * H3;
    float v[9];
    float sum = 0.0f, sq = 0.0f;

#pragma unroll
    for (int i = 0; i < 9; i++) {
        float xv = p[threadIdx.x + i * 256];
        float ge = 0.5f * xv * (1.0f + erff(xv * 0.70710678118654752f));
        v[i] = ge;
        sum += ge;
        sq  += ge * ge;
    }

    __shared__ float ssum[8], ssq[8];
#pragma unroll
    for (int o = 16; o > 0; o >>= 1) {
        sum += __shfl_xor_sync(0xFFFFFFFFu, sum, o);
        sq  += __shfl_xor_sync(0xFFFFFFFFu, sq, o);
    }
    int wid = threadIdx.x >> 5, lid = threadIdx.x & 31;
    if (lid == 0) { ssum[wid] = sum; ssq[wid] = sq; }
    __syncthreads();
    if (threadIdx.x < 32) {
        float s2 = (threadIdx.x < 8) ? ssum[threadIdx.x] : 0.0f;
        float q2 = (threadIdx.x < 8) ? ssq[threadIdx.x]  : 0.0f;
#pragma unroll
        for (int o = 4; o > 0; o >>= 1) {
            s2 += __shfl_xor_sync(0xFFFFFFFFu, s2, o);
            q2 += __shfl_xor_sync(0xFFFFFFFFu, q2, o);
        }
        if (threadIdx.x == 0) { ssum[0] = s2; ssq[0] = q2; }
    }
    __syncthreads();

    float mu   = ssum[0] * (1.0f / H3);
    float var  = ssq[0] * (1.0f / H3) - mu * mu;
    float rstd = rsqrtf(var + 1e-5f);

    size_t o = (size_t)bid * H3;
#pragma unroll
    for (int i = 0; i < 9; i++) {
        int c = threadIdx.x + i * 256;
        hi[o + c] = __float2half_rn((v[i] - mu) * rstd * g[c] + be[c]);
    }
}

// ============================================================================
// 128x128 CTA, 1-term fp16 GEMM (GEMM1/2). 3 stages, occupancy 2.
// 8 warps 2M x 4N, warp 64x32. Dense runtime tile mapping (1-D grid).
// ============================================================================
#define RS        144
#define SEC128    (128 * RS)             // 18432
#define STG128    (2 * SEC128)           // 36864 (A, B)
#define SMEM128   (3 * STG128)           // 110592 -> occ 2
#define OFF_B1    SEC128

__global__ __launch_bounds__(256, 2)
void gemm128_kernel(const __half* __restrict__ Ahi,
                    const __half* __restrict__ B,
                    const float* __restrict__ bias,
                    float* __restrict__ C) {
    // dense tile mapping: consecutive bids share the same N tile
    const int mtiles = g_mpad >> 7;
    const int bid = blockIdx.x;
    if (bid >= mtiles * NT1) return;
    const int row0 = (bid % mtiles) * 128;
    const int col0 = (bid / mtiles) * 128;

    extern __shared__ char smem[];
    const uint32_t sb = smem_u32(smem);
    const int tid  = threadIdx.x;
    const int wid  = tid >> 5;
    const int lane = tid & 31;
    const int wm   = wid >> 2;          // 0..1
    const int wn   = wid & 3;           // 0..3

    const char* baseA = (const char*)(Ahi + (size_t)row0 * KDIM);
    const char* baseB = (const char*)(B   + (size_t)col0 * KDIM);

    const int lr = tid >> 3;
    const int lc = (tid & 7) << 4;

    auto load_stage = [&](uint32_t stg_addr, int chunk) {
        size_t kb = (size_t)chunk * 128 + lc;
        uint32_t sa = stg_addr + (uint32_t)lr * RS + lc;
#pragma unroll
        for (int i = 0; i < 4; i++)
            cp16(sa + i * (32 * RS),
                 baseA + (size_t)(lr + i * 32) * (KDIM * 2) + kb);
#pragma unroll
        for (int i = 0; i < 4; i++)
            cp16(sa + OFF_B1 + i * (32 * RS),
                 baseB + (size_t)(lr + i * 32) * (KDIM * 2) + kb);
        asm volatile("cp.async.commit_group;");
    };

    load_stage(sb, 0);
    load_stage(sb + STG128, 1);
    load_stage(sb + 2 * STG128, 2);

    float acc[4][4][4];
#pragma unroll
    for (int i = 0; i < 4; i++)
#pragma unroll
        for (int j = 0; j < 4; j++)
#pragma unroll
            for (int t = 0; t < 4; t++) acc[i][j][t] = 0.0f;

    const int q = lane >> 3, r8 = lane & 7;
    const uint32_t a_off = (uint32_t)((r8 + (q & 1) * 8) * RS + (q >> 1) * 16);
    const uint32_t b_off = (uint32_t)((r8 + (q >> 1) * 8) * RS + (q & 1) * 16);

    for (int c = 0; c < NCHUNKS; c++) {
        if (c < NCHUNKS - 2)      asm volatile("cp.async.wait_group 2;");
        else if (c == NCHUNKS-2)  asm volatile("cp.async.wait_group 1;");
        else                      asm volatile("cp.async.wait_group 0;");
        __syncthreads();

        const uint32_t stg = sb + (uint32_t)(c % 3) * STG128;
        const uint32_t aH = stg + (uint32_t)(wm * 64) * RS + a_off;
        const uint32_t bB = stg + OFF_B1 + (uint32_t)(wn * 32) * RS + b_off;

#pragma unroll
        for (int ks = 0; ks < 4; ks++) {
            const uint32_t kb = ks * 32;
            uint32_t ah[4][4], bh[4][2];
#pragma unroll
            for (int mt = 0; mt < 4; mt++)
                ldm_x4(ah[mt], aH + mt * (16 * RS) + kb);
#pragma unroll
            for (int np = 0; np < 2; np++) {
                uint32_t t[4];
                ldm_x4(t, bB + np * (16 * RS) + kb);
                bh[2*np][0] = t[0]; bh[2*np][1] = t[1];
                bh[2*np+1][0] = t[2]; bh[2*np+1][1] = t[3];
            }
#pragma unroll
            for (int mt = 0; mt < 4; mt++)
#pragma unroll
                for (int nt = 0; nt < 4; nt++)
                    mma_fp16(acc[mt][nt], ah[mt], bh[nt]);
        }
        __syncthreads();

        if (c + 3 < NCHUNKS) load_stage(stg, c + 3);
    }

    const int mrow = row0 + wm * 64 + (lane >> 2);
    const int ncol = col0 + wn * 32 + (lane & 3) * 2;
#pragma unroll
    for (int mt = 0; mt < 4; mt++) {
        int m = mrow + mt * 16;
#pragma unroll
        for (int nt = 0; nt < 4; nt++) {
            int n = ncol + nt * 8;
            float bx2 = bias[n], by2 = bias[n + 1];
            *(float2*)(C + (size_t)m * H3 + n) =
                make_float2(acc[mt][nt][0] + bx2, acc[mt][nt][1] + by2);
            *(float2*)(C + (size_t)(m + 8) * H3 + n) =
                make_float2(acc[mt][nt][2] + bx2, acc[mt][nt][3] + by2);
        }
    }
}

// ============================================================================
// 256x128 CTA, 1-term fp16 GEMM (GEMM3). 3 stages, occ 1.
// 8 warps 4M x 2N, warp 64x64. Dense runtime tile mapping (1-D grid).
// ============================================================================
#define A_SEC3    (256 * RS)              // 36864
#define B_SEC3    (128 * RS)              // 18432
#define STG256    (A_SEC3 + B_SEC3)       // 55296
#define OFF_B3    A_SEC3
#define SMEM256   (3 * STG256)            // 165888

__global__ __launch_bounds__(256, 1)
void gemm256_kernel(const __half* __restrict__ Ahi,
                    const __half* __restrict__ B,
                    const float* __restrict__ bias,
                    float* __restrict__ C, int N,
                    const int* __restrict__ rowmap) {
    // dense tile mapping: consecutive bids share the same N tile
    const int mtiles = (g_mpad + 255) >> 8;
    const int bid = blockIdx.x;
    if (bid >= mtiles * NT3) return;
    const int row0 = (bid % mtiles) * 256;
    const int col0 = (bid / mtiles) * 128;

    extern __shared__ char smem[];
    const uint32_t sb = smem_u32(smem);
    const int tid  = threadIdx.x;
    const int wid  = tid >> 5;
    const int lane = tid & 31;
    const int wm   = wid >> 1;
    const int wn   = wid & 1;

    const char* baseA = (const char*)(Ahi + (size_t)row0 * KDIM);
    const char* baseB = (const char*)(B   + (size_t)col0 * KDIM);

    const int lr = tid >> 3;
    const int lc = (tid & 7) << 4;

    auto load_stage = [&](uint32_t stg_addr, int chunk) {
        size_t kb = (size_t)chunk * 128 + lc;
        uint32_t sa = stg_addr + (uint32_t)lr * RS + lc;
#pragma unroll
        for (int i = 0; i < 8; i++)
            cp16(sa + i * (32 * RS),
                 baseA + (size_t)(lr + i * 32) * (KDIM * 2) + kb);
#pragma unroll
        for (int i = 0; i < 4; i++)
            cp16(sa + OFF_B3 + i * (32 * RS),
                 baseB + (size_t)(lr + i * 32) * (KDIM * 2) + kb);
        asm volatile("cp.async.commit_group;");
    };

    load_stage(sb, 0);
    load_stage(sb + STG256, 1);
    load_stage(sb + 2 * STG256, 2);

    float acc[4][8][4];
#pragma unroll
    for (int i = 0; i < 4; i++)
#pragma unroll
        for (int j = 0; j < 8; j++)
#pragma unroll
            for (int t = 0; t < 4; t++) acc[i][j][t] = 0.0f;

    const int q = lane >> 3, r8 = lane & 7;
    const uint32_t a_off = (uint32_t)((r8 + (q & 1) * 8) * RS + (q >> 1) * 16);
    const uint32_t b_off = (uint32_t)((r8 + (q >> 1) * 8) * RS + (q & 1) * 16);

    for (int c = 0; c < NCHUNKS; c++) {
        if (c < NCHUNKS - 2)      asm volatile("cp.async.wait_group 2;");
        else if (c == NCHUNKS-2)  asm volatile("cp.async.wait_group 1;");
        else                      asm volatile("cp.async.wait_group 0;");
        __syncthreads();

        const uint32_t stg = sb + (uint32_t)(c % 3) * STG256;
        const uint32_t aH = stg + (uint32_t)(wm * 64) * RS + a_off;
        const uint32_t bB = stg + OFF_B3 + (uint32_t)(wn * 64) * RS + b_off;

#pragma unroll
        for (int ks = 0; ks < 4; ks++) {
            const uint32_t kb = ks * 32;
            uint32_t ah[4][4], bh[8][2];
#pragma unroll
            for (int mt = 0; mt < 4; mt++)
                ldm_x4(ah[mt], aH + mt * (16 * RS) + kb);
#pragma unroll
            for (int np = 0; np < 4; np++) {
                uint32_t t[4];
                ldm_x4(t, bB + np * (16 * RS) + kb);
                bh[2*np][0] = t[0]; bh[2*np][1] = t[1];
                bh[2*np+1][0] = t[2]; bh[2*np+1][1] = t[3];
            }
#pragma unroll
            for (int mt = 0; mt < 4; mt++)
#pragma unroll
                for (int nt = 0; nt < 8; nt++)
                    mma_fp16(acc[mt][nt], ah[mt], bh[nt]);
        }
        __syncthreads();

        if (c + 3 < NCHUNKS) load_stage(stg, c + 3);
    }

    const int mrow = row0 + wm * 64 + (lane >> 2);
    const int ncol = col0 + wn * 64 + (lane & 3) * 2;
#pragma unroll
    for (int mt = 0; mt < 4; mt++) {
        int m0 = mrow + mt * 16;
        int o0 = rowmap[m0];
        int o1 = rowmap[m0 + 8];
#pragma unroll
        for (int nt = 0; nt < 8; nt++) {
            int n = ncol + nt * 8;
            if (n < N) {
                float bx = bias[n], by = bias[n + 1];
                if (o0 >= 0)
                    *(float2*)(C + (size_t)o0 * N + n) =
                        make_float2(acc[mt][nt][0] + bx, acc[mt][nt][1] + by);
                if (o1 >= 0)
                    *(float2*)(C + (size_t)o1 * N + n) =
                        make_float2(acc[mt][nt][2] + bx, acc[mt][nt][3] + by);
            }
        }
    }
}

// ---------------- broadcast const output row to all masked rows ----------------
__global__ void broadcast_kernel(const void* __restrict__ mask,
                                 float* __restrict__ out) {
    int row = blockIdx.x;
    int cs = g_const_slot;
    if (cs < 0 || row == cs) return;
    if (read_mask(mask, row, g_mask_mode)) return;
    const float2* src = (const float2*)(out + (size_t)cs * Vv);
    float2* dst = (float2*)(out + (size_t)row * Vv);
    for (int i = threadIdx.x; i < Vv / 2; i += blockDim.x)
        dst[i] = src[i];
}

// ---------------- launch ----------------
#define TRB_WOUT 2048

extern "C" void kernel_launch(void* const* d_in, const int* in_sizes, int n_in,
                              void* d_out, int out_size) {
    const float* x    = (const float*)d_in[0];
    const int*   left = (const int*)  d_in[1];
    const int*   rght = (const int*)  d_in[2];
    const void*  mask =               d_in[3];
    const float* pos  = (const float*)d_in[4];
    const float* W1   = (const float*)d_in[5];
    const float* b1   = (const float*)d_in[6];
    const float* g1   = (const float*)d_in[7];
    const float* be1  = (const float*)d_in[8];
    const float* W2   = (const float*)d_in[9];
    const float* b2   = (const float*)d_in[10];
    const float* g2   = (const float*)d_in[11];
    const float* be2  = (const float*)d_in[12];
    const float* Wout = (const float*)d_in[13];
    const float* bout = (const float*)d_in[14];
    float* out = (float*)d_out;

    __half *act_hi, *w1h, *w2h, *woh;
    float* bufF;
    int* rowmap;
    cudaGetSymbolAddress((void**)&act_hi, g_act_hi);
    cudaGetSymbolAddress((void**)&bufF,   g_bufF);
    cudaGetSymbolAddress((void**)&w1h,    g_w1_h);
    cudaGetSymbolAddress((void**)&w2h,    g_w2_h);
    cudaGetSymbolAddress((void**)&woh,    g_wo_h);
    cudaGetSymbolAddress((void**)&rowmap, g_rowmap);

    cudaFuncSetAttribute(gemm128_kernel,
                         cudaFuncAttributeMaxDynamicSharedMemorySize, SMEM128);
    cudaFuncSetAttribute(gemm256_kernel,
                         cudaFuncAttributeMaxDynamicSharedMemorySize, SMEM256);

    // idx 0: compaction (includes mask-dtype detect)
    compact_kernel<<<1, 1024>>>(mask);

    // idx 1: concat + fused W1 transpose
    concat_fused_kernel<<<MC + TRB_SMALL, 256>>>(x, left, rght, pos, act_hi, W1, w1h);

    // idx 2: GEMM1 (dense 1-D grid)
    gemm128_kernel<<<(MC / 128) * NT1, 256, SMEM128>>>(act_hi, w1h, b1, bufF);

    // idx 3: GELU+LN 1 + fused W2 transpose (profiled slot)
    gelu_ln_fused_kernel<<<MC + TRB_SMALL, 256>>>(
        bufF, g1, be1, act_hi, W2, w2h, H3, TRB_SMALL);

    // idx 4: GEMM2 (dense 1-D grid)
    gemm128_kernel<<<(MC / 128) * NT1, 256, SMEM128>>>(act_hi, w2h, b2, bufF);

    // idx 5: GELU+LN 2 + fused Wout transpose
    gelu_ln_fused_kernel<<<MC + TRB_WOUT, 256>>>(
        bufF, g2, be2, act_hi, Wout, woh, Vv, TRB_WOUT);

    // idx 6: GEMM3 (dense 1-D grid) with row scatter
    gemm256_kernel<<<(MC / 256) * NT3, 256, SMEM256>>>(
        act_hi, woh, bout, out, Vv, rowmap);

    // idx 7: fill masked rows with the constant output row
    broadcast_kernel<<<Mrows, 256>>>(mask, out);
}

// round 16
// speedup vs baseline: 1.0130x; 1.0130x over previous
#include <cuda_runtime.h>
#include <cuda_fp16.h>
#include <math.h>
#include <stdint.h>

// ---------------- problem constants ----------------
#define Ss    512
#define Hh    768
#define Vv    30522
#define Pp    512
#define H3    2304
#define Mrows 4096
#define KDIM  2304
#define NCHUNKS 36          // 2304 / 64
#define VPAD  30592
#define MC    4352          // max compact rows

// ---------------- device scratch (allocation-free) ----------------
__device__ __half g_act_hi[(size_t)MC * KDIM];
__device__ float  g_bufF [(size_t)MC * KDIM];
__device__ __half g_w1_h[(size_t)H3 * KDIM];
__device__ __half g_w2_h[(size_t)H3 * KDIM];
__device__ __half g_wo_h[(size_t)VPAD * KDIM];   // pad rows stay zero
__device__ int    g_mask_mode;
__device__ int    g_rowmap[MC];
__device__ int    g_mkept;
__device__ int    g_mpad;
__device__ int    g_const_slot;

// ---------------- helpers ----------------
__device__ __forceinline__ uint32_t smem_u32(const void* p) {
    uint32_t a;
    asm("{ .reg .u64 t; cvta.to.shared.u64 t, %1; cvt.u32.u64 %0, t; }"
        : "=r"(a) : "l"(p));
    return a;
}
__device__ __forceinline__ void cp16(uint32_t s, const void* g) {
    asm volatile("cp.async.cg.shared.global [%0], [%1], 16;" :: "r"(s), "l"(g));
}
__device__ __forceinline__ void ldm_x4(uint32_t* r, uint32_t addr) {
    asm volatile("ldmatrix.sync.aligned.m8n8.x4.shared.b16 {%0,%1,%2,%3}, [%4];"
                 : "=r"(r[0]), "=r"(r[1]), "=r"(r[2]), "=r"(r[3]) : "r"(addr));
}
__device__ __forceinline__ void mma_fp16(float* c, const uint32_t* a, const uint32_t* b) {
    asm volatile(
        "mma.sync.aligned.m16n8k16.row.col.f32.f16.f16.f32 "
        "{%0,%1,%2,%3}, {%4,%5,%6,%7}, {%8,%9}, {%0,%1,%2,%3};"
        : "+f"(c[0]), "+f"(c[1]), "+f"(c[2]), "+f"(c[3])
        : "r"(a[0]), "r"(a[1]), "r"(a[2]), "r"(a[3]), "r"(b[0]), "r"(b[1]));
}
__device__ __forceinline__ bool read_mask(const void* mask, int row, int mode) {
    if (mode == 0)      return ((const int*)mask)[row] != 0;
    else if (mode == 1) return ((const float*)mask)[row] != 0.0f;
    else                return ((const unsigned char*)mask)[row] != 0;
}

// ---------------- compact (includes mask-dtype detect) ----------------
__global__ void compact_kernel(const void* __restrict__ mask) {
    __shared__ int cnt[1024];
    __shared__ int firstm;
    __shared__ unsigned int s_not01, s_notf;
    __shared__ int s_mode;
    int t = threadIdx.x;
    if (t == 0) { firstm = 0x7FFFFFFF; s_not01 = 0u; s_notf = 0u; }
    __syncthreads();
    {
        unsigned int v = ((const unsigned int*)mask)[t];
        unsigned int a = v & ~1u;
        unsigned int b = (v != 0u && v != 0x3F800000u) ? 1u : 0u;
        if (a) atomicOr(&s_not01, a);
        if (b) atomicOr(&s_notf, 1u);
    }
    __syncthreads();
    if (t == 0) {
        int mode = (s_not01 == 0u) ? 0 : ((s_notf == 0u) ? 1 : 2);
        s_mode = mode;
        g_mask_mode = mode;
    }
    __syncthreads();
    int mode = s_mode;

    bool keep[4];
    int c = 0, fm = 0x7FFFFFFF;
#pragma unroll
    for (int j = 0; j < 4; j++) {
        int row = t * 4 + j;
        bool m = read_mask(mask, row, mode);
        keep[j] = m;
        c += m ? 1 : 0;
        if (!m && row < fm) fm = row;
    }
    if (fm != 0x7FFFFFFF) atomicMin(&firstm, fm);
    cnt[t] = c;
    __syncthreads();
    for (int o = 1; o < 1024; o <<= 1) {
        int v = (t >= o) ? cnt[t - o] : 0;
        __syncthreads();
        cnt[t] += v;
        __syncthreads();
    }
    int off = cnt[t] - c;
#pragma unroll
    for (int j = 0; j < 4; j++)
        if (keep[j]) g_rowmap[off++] = t * 4 + j;
    __syncthreads();
    int total = cnt[1023];
    if (t == 0) {
        int cs = (firstm == 0x7FFFFFFF) ? -1 : firstm;
        g_mkept = total;
        g_rowmap[total] = cs;
        g_const_slot = cs;
        g_mpad = ((total + 1 + 127) / 128) * 128;
    }
    __syncthreads();
    int tot1 = cnt[1023] + 1;
    for (int i = tot1 + t; i < MC; i += 1024) g_rowmap[i] = -1;
}

// ---------------- weight transpose to fp16: W[K,N] -> T[N,K] ----------------
__global__ void transpose_half_kernel(const float* __restrict__ W,
                                      __half* __restrict__ T,
                                      int K, int N) {
    __shared__ float t[32][33];
    int tx = threadIdx.x & 31, ty = threadIdx.x >> 5;
    int n0 = blockIdx.x * 32, k0 = blockIdx.y * 32;
#pragma unroll
    for (int i = 0; i < 4; i++) {
        int k = k0 + ty + i * 8;
        int n = n0 + tx;
        t[ty + i * 8][tx] = (n < N) ? W[(size_t)k * N + n] : 0.0f;
    }
    __syncthreads();
#pragma unroll
    for (int i = 0; i < 4; i++) {
        int n = n0 + ty + i * 8;
        int k = k0 + tx;
        if (n < N)
            T[(size_t)n * K + k] = __float2half_rn(t[tx][ty + i * 8]);
    }
}

// ---------------- concat build (compact domain) -> fp16 ----------------
__global__ void concat_kernel(const float* __restrict__ x,
                              const int* __restrict__ left,
                              const int* __restrict__ right,
                              const float* __restrict__ pos_table,
                              __half* __restrict__ hi) {
    int ci = blockIdx.x;
    int mpad = g_mpad, mk = g_mkept;
    if (ci >= mpad) return;
    size_t o = (size_t)ci * H3;

    if (ci >= mk) {
        __half hv = (ci == mk) ? __float2half_rn(-100.0f) : __float2half_rn(0.0f);
        for (int i = threadIdx.x; i < H3; i += blockDim.x)
            hi[o + i] = hv;
        return;
    }

    int row = g_rowmap[ci];
    int b = row >> 9;
    int s = row & (Ss - 1);
    int l = left[row], r = right[row];
    int rel = s - l;
    rel = rel < 0 ? 0 : (rel > (Pp - 1) ? (Pp - 1) : rel);

    const float* xl = x + ((size_t)b * Ss + l) * Hh;
    const float* xr = x + ((size_t)b * Ss + r) * Hh;
    const float* pp = pos_table + (size_t)rel * Hh;

    for (int i = threadIdx.x; i < Hh; i += blockDim.x) {
        hi[o + i]          = __float2half_rn(xl[i]);
        hi[o + Hh + i]     = __float2half_rn(xr[i]);
        hi[o + 2*Hh + i]   = __float2half_rn(pp[i]);
    }
}

// ---------------- GELU + LayerNorm (fp32 in) -> fp16 out ----------------
__global__ __launch_bounds__(256, 4)
void gelu_ln_kernel(const float* __restrict__ in,
                    const float* __restrict__ g,
                    const float* __restrict__ be,
                    __half* __restrict__ hi) {
    if ((int)blockIdx.x >= g_mpad) return;
    const float* p = in + (size_t)blockIdx.x * H3;
    float v[9];
    float sum = 0.0f, sq = 0.0f;

#pragma unroll
    for (int i = 0; i < 9; i++) {
        float xv = p[threadIdx.x + i * 256];
        float ge = 0.5f * xv * (1.0f + erff(xv * 0.70710678118654752f));
        v[i] = ge;
        sum += ge;
        sq  += ge * ge;
    }

    __shared__ float ssum[8], ssq[8];
#pragma unroll
    for (int o = 16; o > 0; o >>= 1) {
        sum += __shfl_xor_sync(0xFFFFFFFFu, sum, o);
        sq  += __shfl_xor_sync(0xFFFFFFFFu, sq, o);
    }
    int wid = threadIdx.x >> 5, lid = threadIdx.x & 31;
    if (lid == 0) { ssum[wid] = sum; ssq[wid] = sq; }
    __syncthreads();
    if (threadIdx.x < 32) {
        float s2 = (threadIdx.x < 8) ? ssum[threadIdx.x] : 0.0f;
        float q2 = (threadIdx.x < 8) ? ssq[threadIdx.x]  : 0.0f;
#pragma unroll
        for (int o = 4; o > 0; o >>= 1) {
            s2 += __shfl_xor_sync(0xFFFFFFFFu, s2, o);
            q2 += __shfl_xor_sync(0xFFFFFFFFu, q2, o);
        }
        if (threadIdx.x == 0) { ssum[0] = s2; ssq[0] = q2; }
    }
    __syncthreads();

    float mu   = ssum[0] * (1.0f / H3);
    float var  = ssq[0] * (1.0f / H3) - mu * mu;
    float rstd = rsqrtf(var + 1e-5f);

    size_t o = (size_t)blockIdx.x * H3;
#pragma unroll
    for (int i = 0; i < 9; i++) {
        int c = threadIdx.x + i * 256;
        hi[o + c] = __float2half_rn((v[i] - mu) * rstd * g[c] + be[c]);
    }
}

// ============================================================================
// 128x128 CTA, 1-term fp16 GEMM (GEMM1/2). 3 stages, occupancy 2.
// 8 warps 2M x 4N, warp 64x32. Single-barrier mainloop with early prefetch.
// ============================================================================
#define RS        144
#define SEC128    (128 * RS)             // 18432
#define STG128    (2 * SEC128)           // 36864 (A, B)
#define SMEM128   (3 * STG128)           // 110592 -> occ 2
#define OFF_B1    SEC128

__global__ __launch_bounds__(256, 2)
void gemm128_kernel(const __half* __restrict__ Ahi,
                    const __half* __restrict__ B,
                    const float* __restrict__ bias,
                    float* __restrict__ C) {
    if ((int)blockIdx.x * 128 >= g_mpad) return;
    extern __shared__ char smem[];
    const uint32_t sb = smem_u32(smem);
    const int tid  = threadIdx.x;
    const int wid  = tid >> 5;
    const int lane = tid & 31;
    const int wm   = wid >> 2;          // 0..1
    const int wn   = wid & 3;           // 0..3
    const int row0 = blockIdx.x * 128;
    const int col0 = blockIdx.y * 128;

    const char* baseA = (const char*)(Ahi + (size_t)row0 * KDIM);
    const char* baseB = (const char*)(B   + (size_t)col0 * KDIM);

    const int lr = tid >> 3;
    const int lc = (tid & 7) << 4;

    auto load_stage = [&](uint32_t stg_addr, int chunk) {
        size_t kb = (size_t)chunk * 128 + lc;
        uint32_t sa = stg_addr + (uint32_t)lr * RS + lc;
#pragma unroll
        for (int i = 0; i < 4; i++)
            cp16(sa + i * (32 * RS),
                 baseA + (size_t)(lr + i * 32) * (KDIM * 2) + kb);
#pragma unroll
        for (int i = 0; i < 4; i++)
            cp16(sa + OFF_B1 + i * (32 * RS),
                 baseB + (size_t)(lr + i * 32) * (KDIM * 2) + kb);
        asm volatile("cp.async.commit_group;");
    };

    load_stage(sb, 0);
    load_stage(sb + STG128, 1);
    load_stage(sb + 2 * STG128, 2);

    float acc[4][4][4];
#pragma unroll
    for (int i = 0; i < 4; i++)
#pragma unroll
        for (int j = 0; j < 4; j++)
#pragma unroll
            for (int t = 0; t < 4; t++) acc[i][j][t] = 0.0f;

    const int q = lane >> 3, r8 = lane & 7;
    const uint32_t a_off = (uint32_t)((r8 + (q & 1) * 8) * RS + (q >> 1) * 16);
    const uint32_t b_off = (uint32_t)((r8 + (q >> 1) * 8) * RS + (q & 1) * 16);

    for (int c = 0; c < NCHUNKS; c++) {
        if (c == 0)               asm volatile("cp.async.wait_group 2;");
        else if (c < NCHUNKS - 1) asm volatile("cp.async.wait_group 1;");
        else                      asm volatile("cp.async.wait_group 0;");
        __syncthreads();

        // early prefetch into the stage freed by the previous iteration
        if (c >= 1 && c + 2 < NCHUNKS)
            load_stage(sb + (uint32_t)((c - 1) % 3) * STG128, c + 2);

        const uint32_t stg = sb + (uint32_t)(c % 3) * STG128;
        const uint32_t aH = stg + (uint32_t)(wm * 64) * RS + a_off;
        const uint32_t bB = stg + OFF_B1 + (uint32_t)(wn * 32) * RS + b_off;

#pragma unroll
        for (int ks = 0; ks < 4; ks++) {
            const uint32_t kb = ks * 32;
            uint32_t ah[4][4], bh[4][2];
#pragma unroll
            for (int mt = 0; mt < 4; mt++)
                ldm_x4(ah[mt], aH + mt * (16 * RS) + kb);
#pragma unroll
            for (int np = 0; np < 2; np++) {
                uint32_t t[4];
                ldm_x4(t, bB + np * (16 * RS) + kb);
                bh[2*np][0] = t[0]; bh[2*np][1] = t[1];
                bh[2*np+1][0] = t[2]; bh[2*np+1][1] = t[3];
            }
#pragma unroll
            for (int mt = 0; mt < 4; mt++)
#pragma unroll
                for (int nt = 0; nt < 4; nt++)
                    mma_fp16(acc[mt][nt], ah[mt], bh[nt]);
        }
    }

    const int mrow = row0 + wm * 64 + (lane >> 2);
    const int ncol = col0 + wn * 32 + (lane & 3) * 2;
#pragma unroll
    for (int mt = 0; mt < 4; mt++) {
        int m = mrow + mt * 16;
#pragma unroll
        for (int nt = 0; nt < 4; nt++) {
            int n = ncol + nt * 8;
            float bx2 = bias[n], by2 = bias[n + 1];
            *(float2*)(C + (size_t)m * H3 + n) =
                make_float2(acc[mt][nt][0] + bx2, acc[mt][nt][1] + by2);
            *(float2*)(C + (size_t)(m + 8) * H3 + n) =
                make_float2(acc[mt][nt][2] + bx2, acc[mt][nt][3] + by2);
        }
    }
}

// ============================================================================
// 256x128 CTA, 1-term fp16 GEMM (GEMM3). 3 stages, occ 1.
// 8 warps 4M x 2N, warp 64x64. Single-barrier mainloop with early prefetch.
// ============================================================================
#define A_SEC3    (256 * RS)              // 36864
#define B_SEC3    (128 * RS)              // 18432
#define STG256    (A_SEC3 + B_SEC3)       // 55296
#define OFF_B3    A_SEC3
#define SMEM256   (3 * STG256)            // 165888

__global__ __launch_bounds__(256, 1)
void gemm256_kernel(const __half* __restrict__ Ahi,
                    const __half* __restrict__ B,
                    const float* __restrict__ bias,
                    float* __restrict__ C, int N,
                    const int* __restrict__ rowmap) {
    const int row0 = blockIdx.x * 256;
    if (row0 >= g_mpad) return;

    extern __shared__ char smem[];
    const uint32_t sb = smem_u32(smem);
    const int tid  = threadIdx.x;
    const int wid  = tid >> 5;
    const int lane = tid & 31;
    const int wm   = wid >> 1;
    const int wn   = wid & 1;
    const int col0 = blockIdx.y * 128;

    const char* baseA = (const char*)(Ahi + (size_t)row0 * KDIM);
    const char* baseB = (const char*)(B   + (size_t)col0 * KDIM);

    const int lr = tid >> 3;
    const int lc = (tid & 7) << 4;

    auto load_stage = [&](uint32_t stg_addr, int chunk) {
        size_t kb = (size_t)chunk * 128 + lc;
        uint32_t sa = stg_addr + (uint32_t)lr * RS + lc;
#pragma unroll
        for (int i = 0; i < 8; i++)
            cp16(sa + i * (32 * RS),
                 baseA + (size_t)(lr + i * 32) * (KDIM * 2) + kb);
#pragma unroll
        for (int i = 0; i < 4; i++)
            cp16(sa + OFF_B3 + i * (32 * RS),
                 baseB + (size_t)(lr + i * 32) * (KDIM * 2) + kb);
        asm volatile("cp.async.commit_group;");
    };

    load_stage(sb, 0);
    load_stage(sb + STG256, 1);
    load_stage(sb + 2 * STG256, 2);

    float acc[4][8][4];
#pragma unroll
    for (int i = 0; i < 4; i++)
#pragma unroll
        for (int j = 0; j < 8; j++)
#pragma unroll
            for (int t = 0; t < 4; t++) acc[i][j][t] = 0.0f;

    const int q = lane >> 3, r8 = lane & 7;
    const uint32_t a_off = (uint32_t)((r8 + (q & 1) * 8) * RS + (q >> 1) * 16);
    const uint32_t b_off = (uint32_t)((r8 + (q >> 1) * 8) * RS + (q & 1) * 16);

    for (int c = 0; c < NCHUNKS; c++) {
        if (c == 0)               asm volatile("cp.async.wait_group 2;");
        else if (c < NCHUNKS - 1) asm volatile("cp.async.wait_group 1;");
        else                      asm volatile("cp.async.wait_group 0;");
        __syncthreads();

        // early prefetch into the stage freed by the previous iteration
        if (c >= 1 && c + 2 < NCHUNKS)
            load_stage(sb + (uint32_t)((c - 1) % 3) * STG256, c + 2);

        const uint32_t stg = sb + (uint32_t)(c % 3) * STG256;
        const uint32_t aH = stg + (uint32_t)(wm * 64) * RS + a_off;
        const uint32_t bB = stg + OFF_B3 + (uint32_t)(wn * 64) * RS + b_off;

#pragma unroll
        for (int ks = 0; ks < 4; ks++) {
            const uint32_t kb = ks * 32;
            uint32_t ah[4][4], bh[8][2];
#pragma unroll
            for (int mt = 0; mt < 4; mt++)
                ldm_x4(ah[mt], aH + mt * (16 * RS) + kb);
#pragma unroll
            for (int np = 0; np < 4; np++) {
                uint32_t t[4];
                ldm_x4(t, bB + np * (16 * RS) + kb);
                bh[2*np][0] = t[0]; bh[2*np][1] = t[1];
                bh[2*np+1][0] = t[2]; bh[2*np+1][1] = t[3];
            }
#pragma unroll
            for (int mt = 0; mt < 4; mt++)
#pragma unroll
                for (int nt = 0; nt < 8; nt++)
                    mma_fp16(acc[mt][nt], ah[mt], bh[nt]);
        }
    }

    const int mrow = row0 + wm * 64 + (lane >> 2);
    const int ncol = col0 + wn * 64 + (lane & 3) * 2;
#pragma unroll
    for (int mt = 0; mt < 4; mt++) {
        int m0 = mrow + mt * 16;
        int o0 = rowmap[m0];
        int o1 = rowmap[m0 + 8];
#pragma unroll
        for (int nt = 0; nt < 8; nt++) {
            int n = ncol + nt * 8;
            if (n < N) {
                float bx = bias[n], by = bias[n + 1];
                if (o0 >= 0)
                    *(float2*)(C + (size_t)o0 * N + n) =
                        make_float2(acc[mt][nt][0] + bx, acc[mt][nt][1] + by);
                if (o1 >= 0)
                    *(float2*)(C + (size_t)o1 * N + n) =
                        make_float2(acc[mt][nt][2] + bx, acc[mt][nt][3] + by);
            }
        }
    }
}

// ---------------- broadcast const output row to all masked rows ----------------
__global__ void broadcast_kernel(const void* __restrict__ mask,
                                 float* __restrict__ out) {
    int row = blockIdx.x;
    int cs = g_const_slot;
    if (cs < 0 || row == cs) return;
    if (read_mask(mask, row, g_mask_mode)) return;
    const float2* src = (const float2*)(out + (size_t)cs * Vv);
    float2* dst = (float2*)(out + (size_t)row * Vv);
    for (int i = threadIdx.x; i < Vv / 2; i += blockDim.x)
        dst[i] = src[i];
}

// ---------------- launch ----------------
extern "C" void kernel_launch(void* const* d_in, const int* in_sizes, int n_in,
                              void* d_out, int out_size) {
    const float* x    = (const float*)d_in[0];
    const int*   left = (const int*)  d_in[1];
    const int*   rght = (const int*)  d_in[2];
    const void*  mask =               d_in[3];
    const float* pos  = (const float*)d_in[4];
    const float* W1   = (const float*)d_in[5];
    const float* b1   = (const float*)d_in[6];
    const float* g1   = (const float*)d_in[7];
    const float* be1  = (const float*)d_in[8];
    const float* W2   = (const float*)d_in[9];
    const float* b2   = (const float*)d_in[10];
    const float* g2   = (const float*)d_in[11];
    const float* be2  = (const float*)d_in[12];
    const float* Wout = (const float*)d_in[13];
    const float* bout = (const float*)d_in[14];
    float* out = (float*)d_out;

    __half *act_hi, *w1h, *w2h, *woh;
    float* bufF;
    int* rowmap;
    cudaGetSymbolAddress((void**)&act_hi, g_act_hi);
    cudaGetSymbolAddress((void**)&bufF,   g_bufF);
    cudaGetSymbolAddress((void**)&w1h,    g_w1_h);
    cudaGetSymbolAddress((void**)&w2h,    g_w2_h);
    cudaGetSymbolAddress((void**)&woh,    g_wo_h);
    cudaGetSymbolAddress((void**)&rowmap, g_rowmap);

    cudaFuncSetAttribute(gemm128_kernel,
                         cudaFuncAttributeMaxDynamicSharedMemorySize, SMEM128);
    cudaFuncSetAttribute(gemm256_kernel,
                         cudaFuncAttributeMaxDynamicSharedMemorySize, SMEM256);

    // idx 0: compaction (includes mask-dtype detect)
    compact_kernel<<<1, 1024>>>(mask);

    // idx 1: concat
    concat_kernel<<<MC, 256>>>(x, left, rght, pos, act_hi);

    // idx 2: W1 transpose
    transpose_half_kernel<<<dim3(H3 / 32, KDIM / 32), 256>>>(W1, w1h, KDIM, H3);

    // idx 3: GEMM1 (profiled slot)
    gemm128_kernel<<<dim3(MC / 128, H3 / 128), 256, SMEM128>>>(
        act_hi, w1h, b1, bufF);

    // idx 4: W2 transpose
    transpose_half_kernel<<<dim3(H3 / 32, KDIM / 32), 256>>>(W2, w2h, KDIM, H3);

    // idx 5: GELU+LN 1
    gelu_ln_kernel<<<MC, 256>>>(bufF, g1, be1, act_hi);

    // idx 6: GEMM2
    gemm128_kernel<<<dim3(MC / 128, H3 / 128), 256, SMEM128>>>(
        act_hi, w2h, b2, bufF);

    // idx 7: Wout transpose
    transpose_half_kernel<<<dim3((Vv + 31) / 32, KDIM / 32), 256>>>(Wout, woh, KDIM, Vv);

    // idx 8: GELU+LN 2
    gelu_ln_kernel<<<MC, 256>>>(bufF, g2, be2, act_hi);

    // idx 9: GEMM3 with row scatter
    gemm256_kernel<<<dim3(MC / 256, (Vv + 127) / 128), 256, SMEM256>>>(
        act_hi, woh, bout, out, Vv, rowmap);

    // idx 10: fill masked rows with the constant output row
    broadcast_kernel<<<Mrows, 256>>>(mask, out);
}

// round 17
// speedup vs baseline: 1.1925x; 1.1771x over previous
#include <cuda_runtime.h>
#include <cuda_fp16.h>
#include <math.h>
#include <stdint.h>

// ---------------- problem constants ----------------
#define Ss    512
#define Hh    768
#define Vv    30522
#define Pp    512
#define H3    2304
#define Mrows 4096
#define KDIM  2304
#define NCHUNKS 36          // 2304 / 64
#define VPAD  30592
#define MC    4352          // max compact rows

// ---------------- device scratch (allocation-free) ----------------
__device__ __half g_act_hi[(size_t)MC * KDIM];
__device__ float  g_bufF [(size_t)MC * KDIM];
__device__ __half g_w1_h[(size_t)H3 * KDIM];
__device__ __half g_w2_h[(size_t)H3 * KDIM];
__device__ __half g_wo_h[(size_t)VPAD * KDIM];   // pad rows stay zero
__device__ int    g_mask_mode;
__device__ int    g_rowmap[MC];
__device__ int    g_mkept;
__device__ int    g_mpad;
__device__ int    g_const_slot;

// ---------------- helpers ----------------
__device__ __forceinline__ uint32_t smem_u32(const void* p) {
    uint32_t a;
    asm("{ .reg .u64 t; cvta.to.shared.u64 t, %1; cvt.u32.u64 %0, t; }"
        : "=r"(a) : "l"(p));
    return a;
}
__device__ __forceinline__ void cp16(uint32_t s, const void* g) {
    asm volatile("cp.async.cg.shared.global [%0], [%1], 16;" :: "r"(s), "l"(g));
}
__device__ __forceinline__ void ldm_x4(uint32_t* r, uint32_t addr) {
    asm volatile("ldmatrix.sync.aligned.m8n8.x4.shared.b16 {%0,%1,%2,%3}, [%4];"
                 : "=r"(r[0]), "=r"(r[1]), "=r"(r[2]), "=r"(r[3]) : "r"(addr));
}
__device__ __forceinline__ void mma_fp16(float* c, const uint32_t* a, const uint32_t* b) {
    asm volatile(
        "mma.sync.aligned.m16n8k16.row.col.f32.f16.f16.f32 "
        "{%0,%1,%2,%3}, {%4,%5,%6,%7}, {%8,%9}, {%0,%1,%2,%3};"
        : "+f"(c[0]), "+f"(c[1]), "+f"(c[2]), "+f"(c[3])
        : "r"(a[0]), "r"(a[1]), "r"(a[2]), "r"(a[3]), "r"(b[0]), "r"(b[1]));
}
__device__ __forceinline__ bool read_mask(const void* mask, int row, int mode) {
    if (mode == 0)      return ((const int*)mask)[row] != 0;
    else if (mode == 1) return ((const float*)mask)[row] != 0.0f;
    else                return ((const unsigned char*)mask)[row] != 0;
}

// ---------------- compact (includes mask-dtype detect) ----------------
__global__ void compact_kernel(const void* __restrict__ mask) {
    __shared__ int cnt[1024];
    __shared__ int firstm;
    __shared__ unsigned int s_not01, s_notf;
    __shared__ int s_mode;
    int t = threadIdx.x;
    if (t == 0) { firstm = 0x7FFFFFFF; s_not01 = 0u; s_notf = 0u; }
    __syncthreads();
    {
        unsigned int v = ((const unsigned int*)mask)[t];
        unsigned int a = v & ~1u;
        unsigned int b = (v != 0u && v != 0x3F800000u) ? 1u : 0u;
        if (a) atomicOr(&s_not01, a);
        if (b) atomicOr(&s_notf, 1u);
    }
    __syncthreads();
    if (t == 0) {
        int mode = (s_not01 == 0u) ? 0 : ((s_notf == 0u) ? 1 : 2);
        s_mode = mode;
        g_mask_mode = mode;
    }
    __syncthreads();
    int mode = s_mode;

    bool keep[4];
    int c = 0, fm = 0x7FFFFFFF;
#pragma unroll
    for (int j = 0; j < 4; j++) {
        int row = t * 4 + j;
        bool m = read_mask(mask, row, mode);
        keep[j] = m;
        c += m ? 1 : 0;
        if (!m && row < fm) fm = row;
    }
    if (fm != 0x7FFFFFFF) atomicMin(&firstm, fm);
    cnt[t] = c;
    __syncthreads();
    for (int o = 1; o < 1024; o <<= 1) {
        int v = (t >= o) ? cnt[t - o] : 0;
        __syncthreads();
        cnt[t] += v;
        __syncthreads();
    }
    int off = cnt[t] - c;
#pragma unroll
    for (int j = 0; j < 4; j++)
        if (keep[j]) g_rowmap[off++] = t * 4 + j;
    __syncthreads();
    int total = cnt[1023];
    if (t == 0) {
        int cs = (firstm == 0x7FFFFFFF) ? -1 : firstm;
        g_mkept = total;
        g_rowmap[total] = cs;
        g_const_slot = cs;
        g_mpad = ((total + 1 + 127) / 128) * 128;
    }
    __syncthreads();
    int tot1 = cnt[1023] + 1;
    for (int i = tot1 + t; i < MC; i += 1024) g_rowmap[i] = -1;
}

// ---------------- weight transpose to fp16: W[K,N] -> T[N,K] ----------------
__global__ void transpose_half_kernel(const float* __restrict__ W,
                                      __half* __restrict__ T,
                                      int K, int N) {
    __shared__ float t[32][33];
    int tx = threadIdx.x & 31, ty = threadIdx.x >> 5;
    int n0 = blockIdx.x * 32, k0 = blockIdx.y * 32;
#pragma unroll
    for (int i = 0; i < 4; i++) {
        int k = k0 + ty + i * 8;
        int n = n0 + tx;
        t[ty + i * 8][tx] = (n < N) ? W[(size_t)k * N + n] : 0.0f;
    }
    __syncthreads();
#pragma unroll
    for (int i = 0; i < 4; i++) {
        int n = n0 + ty + i * 8;
        int k = k0 + tx;
        if (n < N)
            T[(size_t)n * K + k] = __float2half_rn(t[tx][ty + i * 8]);
    }
}

// ---------------- concat build (compact domain) -> fp16 ----------------
__global__ void concat_kernel(const float* __restrict__ x,
                              const int* __restrict__ left,
                              const int* __restrict__ right,
                              const float* __restrict__ pos_table,
                              __half* __restrict__ hi) {
    int ci = blockIdx.x;
    int mpad = g_mpad, mk = g_mkept;
    if (ci >= mpad) return;
    size_t o = (size_t)ci * H3;

    if (ci >= mk) {
        __half hv = (ci == mk) ? __float2half_rn(-100.0f) : __float2half_rn(0.0f);
        for (int i = threadIdx.x; i < H3; i += blockDim.x)
            hi[o + i] = hv;
        return;
    }

    int row = g_rowmap[ci];
    int b = row >> 9;
    int s = row & (Ss - 1);
    int l = left[row], r = right[row];
    int rel = s - l;
    rel = rel < 0 ? 0 : (rel > (Pp - 1) ? (Pp - 1) : rel);

    const float* xl = x + ((size_t)b * Ss + l) * Hh;
    const float* xr = x + ((size_t)b * Ss + r) * Hh;
    const float* pp = pos_table + (size_t)rel * Hh;

    for (int i = threadIdx.x; i < Hh; i += blockDim.x) {
        hi[o + i]          = __float2half_rn(xl[i]);
        hi[o + Hh + i]     = __float2half_rn(xr[i]);
        hi[o + 2*Hh + i]   = __float2half_rn(pp[i]);
    }
}

// ---------------- GELU + LayerNorm (fp32 in) -> fp16 out ----------------
__global__ __launch_bounds__(256, 4)
void gelu_ln_kernel(const float* __restrict__ in,
                    const float* __restrict__ g,
                    const float* __restrict__ be,
                    __half* __restrict__ hi) {
    if ((int)blockIdx.x >= g_mpad) return;
    const float* p = in + (size_t)blockIdx.x * H3;
    float v[9];
    float sum = 0.0f, sq = 0.0f;

#pragma unroll
    for (int i = 0; i < 9; i++) {
        float xv = p[threadIdx.x + i * 256];
        float ge = 0.5f * xv * (1.0f + erff(xv * 0.70710678118654752f));
        v[i] = ge;
        sum += ge;
        sq  += ge * ge;
    }

    __shared__ float ssum[8], ssq[8];
#pragma unroll
    for (int o = 16; o > 0; o >>= 1) {
        sum += __shfl_xor_sync(0xFFFFFFFFu, sum, o);
        sq  += __shfl_xor_sync(0xFFFFFFFFu, sq, o);
    }
    int wid = threadIdx.x >> 5, lid = threadIdx.x & 31;
    if (lid == 0) { ssum[wid] = sum; ssq[wid] = sq; }
    __syncthreads();
    if (threadIdx.x < 32) {
        float s2 = (threadIdx.x < 8) ? ssum[threadIdx.x] : 0.0f;
        float q2 = (threadIdx.x < 8) ? ssq[threadIdx.x]  : 0.0f;
#pragma unroll
        for (int o = 4; o > 0; o >>= 1) {
            s2 += __shfl_xor_sync(0xFFFFFFFFu, s2, o);
            q2 += __shfl_xor_sync(0xFFFFFFFFu, q2, o);
        }
        if (threadIdx.x == 0) { ssum[0] = s2; ssq[0] = q2; }
    }
    __syncthreads();

    float mu   = ssum[0] * (1.0f / H3);
    float var  = ssq[0] * (1.0f / H3) - mu * mu;
    float rstd = rsqrtf(var + 1e-5f);

    size_t o = (size_t)blockIdx.x * H3;
#pragma unroll
    for (int i = 0; i < 9; i++) {
        int c = threadIdx.x + i * 256;
        hi[o + c] = __float2half_rn((v[i] - mu) * rstd * g[c] + be[c]);
    }
}

// ============================================================================
// 128x128 CTA, 1-term fp16 GEMM. 3 stages, occupancy 2, 8 warps 2M x 4N,
// warp 64x32. Single-barrier mainloop with early prefetch. Shared body;
// epilogue variants: direct (GEMM1/2) or rowmap-scatter + N-bounds (GEMM3).
// ============================================================================
#define RS        144
#define SEC128    (128 * RS)             // 18432
#define STG128    (2 * SEC128)           // 36864 (A, B)
#define SMEM128   (3 * STG128)           // 110592 -> occ 2
#define OFF_B1    SEC128

template <bool SCATTER>
__device__ __forceinline__ void gemm128_body(
    const __half* __restrict__ Ahi, const __half* __restrict__ B,
    const float* __restrict__ bias, float* __restrict__ C, int N,
    const int* __restrict__ rowmap, char* smem) {
    const uint32_t sb = smem_u32(smem);
    const int tid  = threadIdx.x;
    const int wid  = tid >> 5;
    const int lane = tid & 31;
    const int wm   = wid >> 2;          // 0..1
    const int wn   = wid & 3;           // 0..3
    const int row0 = blockIdx.x * 128;
    const int col0 = blockIdx.y * 128;

    const char* baseA = (const char*)(Ahi + (size_t)row0 * KDIM);
    const char* baseB = (const char*)(B   + (size_t)col0 * KDIM);

    const int lr = tid >> 3;
    const int lc = (tid & 7) << 4;

    auto load_stage = [&](uint32_t stg_addr, int chunk) {
        size_t kb = (size_t)chunk * 128 + lc;
        uint32_t sa = stg_addr + (uint32_t)lr * RS + lc;
#pragma unroll
        for (int i = 0; i < 4; i++)
            cp16(sa + i * (32 * RS),
                 baseA + (size_t)(lr + i * 32) * (KDIM * 2) + kb);
#pragma unroll
        for (int i = 0; i < 4; i++)
            cp16(sa + OFF_B1 + i * (32 * RS),
                 baseB + (size_t)(lr + i * 32) * (KDIM * 2) + kb);
        asm volatile("cp.async.commit_group;");
    };

    load_stage(sb, 0);
    load_stage(sb + STG128, 1);
    load_stage(sb + 2 * STG128, 2);

    float acc[4][4][4];
#pragma unroll
    for (int i = 0; i < 4; i++)
#pragma unroll
        for (int j = 0; j < 4; j++)
#pragma unroll
            for (int t = 0; t < 4; t++) acc[i][j][t] = 0.0f;

    const int q = lane >> 3, r8 = lane & 7;
    const uint32_t a_off = (uint32_t)((r8 + (q & 1) * 8) * RS + (q >> 1) * 16);
    const uint32_t b_off = (uint32_t)((r8 + (q >> 1) * 8) * RS + (q & 1) * 16);

    for (int c = 0; c < NCHUNKS; c++) {
        if (c == 0)               asm volatile("cp.async.wait_group 2;");
        else if (c < NCHUNKS - 1) asm volatile("cp.async.wait_group 1;");
        else                      asm volatile("cp.async.wait_group 0;");
        __syncthreads();

        // early prefetch into the stage freed by the previous iteration
        if (c >= 1 && c + 2 < NCHUNKS)
            load_stage(sb + (uint32_t)((c - 1) % 3) * STG128, c + 2);

        const uint32_t stg = sb + (uint32_t)(c % 3) * STG128;
        const uint32_t aH = stg + (uint32_t)(wm * 64) * RS + a_off;
        const uint32_t bB = stg + OFF_B1 + (uint32_t)(wn * 32) * RS + b_off;

#pragma unroll
        for (int ks = 0; ks < 4; ks++) {
            const uint32_t kb = ks * 32;
            uint32_t ah[4][4], bh[4][2];
#pragma unroll
            for (int mt = 0; mt < 4; mt++)
                ldm_x4(ah[mt], aH + mt * (16 * RS) + kb);
#pragma unroll
            for (int np = 0; np < 2; np++) {
                uint32_t t[4];
                ldm_x4(t, bB + np * (16 * RS) + kb);
                bh[2*np][0] = t[0]; bh[2*np][1] = t[1];
                bh[2*np+1][0] = t[2]; bh[2*np+1][1] = t[3];
            }
#pragma unroll
            for (int mt = 0; mt < 4; mt++)
#pragma unroll
                for (int nt = 0; nt < 4; nt++)
                    mma_fp16(acc[mt][nt], ah[mt], bh[nt]);
        }
    }

    const int mrow = row0 + wm * 64 + (lane >> 2);
    const int ncol = col0 + wn * 32 + (lane & 3) * 2;
    if (SCATTER) {
#pragma unroll
        for (int mt = 0; mt < 4; mt++) {
            int m0 = mrow + mt * 16;
            int o0 = rowmap[m0];
            int o1 = rowmap[m0 + 8];
#pragma unroll
            for (int nt = 0; nt < 4; nt++) {
                int n = ncol + nt * 8;
                if (n < N) {
                    float bx = bias[n], by = bias[n + 1];
                    if (o0 >= 0)
                        *(float2*)(C + (size_t)o0 * N + n) =
                            make_float2(acc[mt][nt][0] + bx, acc[mt][nt][1] + by);
                    if (o1 >= 0)
                        *(float2*)(C + (size_t)o1 * N + n) =
                            make_float2(acc[mt][nt][2] + bx, acc[mt][nt][3] + by);
                }
            }
        }
    } else {
#pragma unroll
        for (int mt = 0; mt < 4; mt++) {
            int m = mrow + mt * 16;
#pragma unroll
            for (int nt = 0; nt < 4; nt++) {
                int n = ncol + nt * 8;
                float bx = bias[n], by = bias[n + 1];
                *(float2*)(C + (size_t)m * N + n) =
                    make_float2(acc[mt][nt][0] + bx, acc[mt][nt][1] + by);
                *(float2*)(C + (size_t)(m + 8) * N + n) =
                    make_float2(acc[mt][nt][2] + bx, acc[mt][nt][3] + by);
            }
        }
    }
}

__global__ __launch_bounds__(256, 2)
void gemm128_kernel(const __half* __restrict__ Ahi,
                    const __half* __restrict__ B,
                    const float* __restrict__ bias,
                    float* __restrict__ C) {
    if ((int)blockIdx.x * 128 >= g_mpad) return;
    extern __shared__ char smem[];
    gemm128_body<false>(Ahi, B, bias, C, H3, nullptr, smem);
}

__global__ __launch_bounds__(256, 2)
void gemm128v_kernel(const __half* __restrict__ Ahi,
                     const __half* __restrict__ B,
                     const float* __restrict__ bias,
                     float* __restrict__ C,
                     const int* __restrict__ rowmap) {
    if ((int)blockIdx.x * 128 >= g_mpad) return;
    extern __shared__ char smem[];
    gemm128_body<true>(Ahi, B, bias, C, Vv, rowmap, smem);
}

// ---------------- broadcast const output row to all masked rows ----------------
__global__ void broadcast_kernel(const void* __restrict__ mask,
                                 float* __restrict__ out) {
    int row = blockIdx.x;
    int cs = g_const_slot;
    if (cs < 0 || row == cs) return;
    if (read_mask(mask, row, g_mask_mode)) return;
    const float2* src = (const float2*)(out + (size_t)cs * Vv);
    float2* dst = (float2*)(out + (size_t)row * Vv);
    for (int i = threadIdx.x; i < Vv / 2; i += blockDim.x)
        dst[i] = src[i];
}

// ---------------- launch ----------------
extern "C" void kernel_launch(void* const* d_in, const int* in_sizes, int n_in,
                              void* d_out, int out_size) {
    const float* x    = (const float*)d_in[0];
    const int*   left = (const int*)  d_in[1];
    const int*   rght = (const int*)  d_in[2];
    const void*  mask =               d_in[3];
    const float* pos  = (const float*)d_in[4];
    const float* W1   = (const float*)d_in[5];
    const float* b1   = (const float*)d_in[6];
    const float* g1   = (const float*)d_in[7];
    const float* be1  = (const float*)d_in[8];
    const float* W2   = (const float*)d_in[9];
    const float* b2   = (const float*)d_in[10];
    const float* g2   = (const float*)d_in[11];
    const float* be2  = (const float*)d_in[12];
    const float* Wout = (const float*)d_in[13];
    const float* bout = (const float*)d_in[14];
    float* out = (float*)d_out;

    __half *act_hi, *w1h, *w2h, *woh;
    float* bufF;
    int* rowmap;
    cudaGetSymbolAddress((void**)&act_hi, g_act_hi);
    cudaGetSymbolAddress((void**)&bufF,   g_bufF);
    cudaGetSymbolAddress((void**)&w1h,    g_w1_h);
    cudaGetSymbolAddress((void**)&w2h,    g_w2_h);
    cudaGetSymbolAddress((void**)&woh,    g_wo_h);
    cudaGetSymbolAddress((void**)&rowmap, g_rowmap);

    cudaFuncSetAttribute(gemm128_kernel,
                         cudaFuncAttributeMaxDynamicSharedMemorySize, SMEM128);
    cudaFuncSetAttribute(gemm128v_kernel,
                         cudaFuncAttributeMaxDynamicSharedMemorySize, SMEM128);

    // idx 0: compaction (includes mask-dtype detect)
    compact_kernel<<<1, 1024>>>(mask);

    // idx 1: concat
    concat_kernel<<<MC, 256>>>(x, left, rght, pos, act_hi);

    // idx 2: W1 transpose
    transpose_half_kernel<<<dim3(H3 / 32, KDIM / 32), 256>>>(W1, w1h, KDIM, H3);

    // idx 3: GEMM1 (profiled slot)
    gemm128_kernel<<<dim3(MC / 128, H3 / 128), 256, SMEM128>>>(
        act_hi, w1h, b1, bufF);

    // idx 4: W2 transpose
    transpose_half_kernel<<<dim3(H3 / 32, KDIM / 32), 256>>>(W2, w2h, KDIM, H3);

    // idx 5: GELU+LN 1
    gelu_ln_kernel<<<MC, 256>>>(bufF, g1, be1, act_hi);

    // idx 6: GEMM2
    gemm128_kernel<<<dim3(MC / 128, H3 / 128), 256, SMEM128>>>(
        act_hi, w2h, b2, bufF);

    // idx 7: Wout transpose
    transpose_half_kernel<<<dim3((Vv + 31) / 32, KDIM / 32), 256>>>(Wout, woh, KDIM, Vv);

    // idx 8: GELU+LN 2
    gelu_ln_kernel<<<MC, 256>>>(bufF, g2, be2, act_hi);

    // idx 9: GEMM3 on the proven 128x128/occ-2 config, rowmap scatter
    gemm128v_kernel<<<dim3(MC / 128, (Vv + 127) / 128), 256, SMEM128>>>(
        act_hi, woh, bout, out, rowmap);

    // idx 10: fill masked rows with the constant output row
    broadcast_kernel<<<Mrows, 256>>>(mask, out);
}